// round 1
// baseline (speedup 1.0000x reference)
#include <cuda_runtime.h>
#include <math.h>

// Problem constants
#define TT 4096   // tokens
#define DD 1024   // input dim
#define HH 4096   // hidden dim
#define NE 8      // experts
#define NR (TT*2) // total routed rows (top-2)

// ---------------- device scratch (no allocations allowed) ----------------
static __device__ float g_h[(size_t)NR * HH];   // 128 MB hidden activations
static __device__ int   g_rows[NR];             // gathered token id per row
static __device__ float g_gates[NR];            // gate prob per row
static __device__ int   g_tope[TT * 2];
static __device__ float g_topp[TT * 2];
static __device__ int   g_counts[NE];
static __device__ int   g_seg[NE + 1];
static __device__ int   g_cursor[NE];

// ---------------- tiny setup kernels ----------------
__global__ void init_k() {
    int i = threadIdx.x;
    if (i < NE) g_counts[i] = 0;
}

__global__ void router_k(const float* __restrict__ x,
                         const float* __restrict__ Wc,
                         const float* __restrict__ bc) {
    __shared__ float sWc[NE * DD];   // 32 KB
    for (int i = threadIdx.x; i < NE * DD; i += blockDim.x) sWc[i] = Wc[i];
    __syncthreads();

    int warp = threadIdx.x >> 5;
    int lane = threadIdx.x & 31;
    int t = blockIdx.x * 8 + warp;
    if (t >= TT) return;

    float acc[NE];
#pragma unroll
    for (int e = 0; e < NE; e++) acc[e] = 0.f;

    const float* xr = x + (size_t)t * DD;
    for (int d = lane; d < DD; d += 32) {
        float xv = xr[d];
#pragma unroll
        for (int e = 0; e < NE; e++) acc[e] += xv * sWc[e * DD + d];
    }
#pragma unroll
    for (int e = 0; e < NE; e++) {
#pragma unroll
        for (int o = 16; o; o >>= 1) acc[e] += __shfl_xor_sync(0xffffffffu, acc[e], o);
    }

    if (lane == 0) {
        float l[NE], p[NE];
        float mx = -1e30f;
#pragma unroll
        for (int e = 0; e < NE; e++) { l[e] = acc[e] + bc[e]; mx = fmaxf(mx, l[e]); }
        float s = 0.f;
#pragma unroll
        for (int e = 0; e < NE; e++) { p[e] = expf(l[e] - mx); s += p[e]; }
        float inv = 1.f / s;
#pragma unroll
        for (int e = 0; e < NE; e++) p[e] *= inv;

        // top-2, tie -> lowest index (matches lax.top_k)
        int i0 = 0;
#pragma unroll
        for (int e = 1; e < NE; e++) if (p[e] > p[i0]) i0 = e;
        int i1 = (i0 == 0) ? 1 : 0;
#pragma unroll
        for (int e = 0; e < NE; e++) if (e != i0 && p[e] > p[i1]) i1 = e;

        g_tope[2 * t]     = i0; g_topp[2 * t]     = p[i0];
        g_tope[2 * t + 1] = i1; g_topp[2 * t + 1] = p[i1];
        atomicAdd(&g_counts[i0], 1);
        atomicAdd(&g_counts[i1], 1);
    }
}

__global__ void scan_k() {
    if (threadIdx.x == 0) {
        int s = 0;
        for (int e = 0; e < NE; e++) {
            g_seg[e] = s;
            g_cursor[e] = s;
            s += g_counts[e];
        }
        g_seg[NE] = s;
    }
}

__global__ void scatter_k() {
    int t = blockIdx.x * blockDim.x + threadIdx.x;
    if (t >= TT) return;
#pragma unroll
    for (int k = 0; k < 2; k++) {
        int e = g_tope[2 * t + k];
        float p = g_topp[2 * t + k];
        int pos = atomicAdd(&g_cursor[e], 1);
        g_rows[pos] = t;
        g_gates[pos] = p;
    }
}

// ---------------- SGEMM tiles ----------------
#define BM 128
#define BN 128
#define BK 16

// GEMM1: h[r, n] = relu( sum_k x[tok[r], k] * W1[e, n, k] + b1[e, n] )
__global__ __launch_bounds__(256)
void gemm1_k(const float* __restrict__ x,
             const float* __restrict__ W1,
             const float* __restrict__ b1) {
    int e = blockIdx.z;
    int seg0 = g_seg[e];
    int nrows = g_seg[e + 1] - seg0;
    int m0 = blockIdx.y * BM;
    if (m0 >= nrows) return;
    int n0 = blockIdx.x * BN;

    __shared__ __align__(16) float As[BK][BM];
    __shared__ __align__(16) float Bs[BK][BN];
    __shared__ int stok[BM];

    int tid = threadIdx.x;
    if (tid < BM) {
        int m = m0 + tid;
        stok[tid] = (m < nrows) ? g_rows[seg0 + m] : 0;  // clamp: junk rows never stored
    }
    __syncthreads();

    int lm = tid >> 1;           // 0..127 row within tile for loads
    int lk = (tid & 1) * 8;      // k offset 0 or 8
    const float* Arow = x + (size_t)stok[lm] * DD;
    const float* Brow = W1 + ((size_t)e * HH + (size_t)(n0 + lm)) * DD;

    int tx = tid & 15, ty = tid >> 4;
    float acc[8][8];
#pragma unroll
    for (int i = 0; i < 8; i++)
#pragma unroll
        for (int j = 0; j < 8; j++) acc[i][j] = 0.f;

    for (int k0 = 0; k0 < DD; k0 += BK) {
        float4 a0 = *reinterpret_cast<const float4*>(Arow + k0 + lk);
        float4 a1 = *reinterpret_cast<const float4*>(Arow + k0 + lk + 4);
        float4 c0 = *reinterpret_cast<const float4*>(Brow + k0 + lk);
        float4 c1 = *reinterpret_cast<const float4*>(Brow + k0 + lk + 4);
        __syncthreads();
        As[lk + 0][lm] = a0.x; As[lk + 1][lm] = a0.y; As[lk + 2][lm] = a0.z; As[lk + 3][lm] = a0.w;
        As[lk + 4][lm] = a1.x; As[lk + 5][lm] = a1.y; As[lk + 6][lm] = a1.z; As[lk + 7][lm] = a1.w;
        Bs[lk + 0][lm] = c0.x; Bs[lk + 1][lm] = c0.y; Bs[lk + 2][lm] = c0.z; Bs[lk + 3][lm] = c0.w;
        Bs[lk + 4][lm] = c1.x; Bs[lk + 5][lm] = c1.y; Bs[lk + 6][lm] = c1.z; Bs[lk + 7][lm] = c1.w;
        __syncthreads();
#pragma unroll
        for (int kk = 0; kk < BK; kk++) {
            float4 ra0 = *reinterpret_cast<const float4*>(&As[kk][ty * 8]);
            float4 ra1 = *reinterpret_cast<const float4*>(&As[kk][ty * 8 + 4]);
            float4 rb0 = *reinterpret_cast<const float4*>(&Bs[kk][tx * 8]);
            float4 rb1 = *reinterpret_cast<const float4*>(&Bs[kk][tx * 8 + 4]);
            float ra[8] = {ra0.x, ra0.y, ra0.z, ra0.w, ra1.x, ra1.y, ra1.z, ra1.w};
            float rb[8] = {rb0.x, rb0.y, rb0.z, rb0.w, rb1.x, rb1.y, rb1.z, rb1.w};
#pragma unroll
            for (int i = 0; i < 8; i++)
#pragma unroll
                for (int j = 0; j < 8; j++) acc[i][j] += ra[i] * rb[j];
        }
    }

    const float* b1e = b1 + (size_t)e * HH + n0 + tx * 8;
    float bj[8];
#pragma unroll
    for (int j = 0; j < 8; j++) bj[j] = b1e[j];

#pragma unroll
    for (int i = 0; i < 8; i++) {
        int m = ty * 8 + i;
        if (m0 + m < nrows) {
            float* hr = g_h + (size_t)(seg0 + m0 + m) * HH + n0 + tx * 8;
            float4 v0, v1;
            v0.x = fmaxf(acc[i][0] + bj[0], 0.f);
            v0.y = fmaxf(acc[i][1] + bj[1], 0.f);
            v0.z = fmaxf(acc[i][2] + bj[2], 0.f);
            v0.w = fmaxf(acc[i][3] + bj[3], 0.f);
            v1.x = fmaxf(acc[i][4] + bj[4], 0.f);
            v1.y = fmaxf(acc[i][5] + bj[5], 0.f);
            v1.z = fmaxf(acc[i][6] + bj[6], 0.f);
            v1.w = fmaxf(acc[i][7] + bj[7], 0.f);
            *reinterpret_cast<float4*>(hr) = v0;
            *reinterpret_cast<float4*>(hr + 4) = v1;
        }
    }
}

// GEMM2: out[tok, n] += gate * ( sum_h h[r, h] * W2[e, n, h] + b2[e, n] )
__global__ __launch_bounds__(256)
void gemm2_k(const float* __restrict__ W2,
             const float* __restrict__ b2,
             float* __restrict__ out) {
    int e = blockIdx.z;
    int seg0 = g_seg[e];
    int nrows = g_seg[e + 1] - seg0;
    int m0 = blockIdx.y * BM;
    if (m0 >= nrows) return;
    int n0 = blockIdx.x * BN;

    __shared__ __align__(16) float As[BK][BM];
    __shared__ __align__(16) float Bs[BK][BN];
    __shared__ int stok[BM];
    __shared__ float sgate[BM];

    int tid = threadIdx.x;
    if (tid < BM) {
        int m = m0 + tid;
        if (m < nrows) {
            stok[tid] = g_rows[seg0 + m];
            sgate[tid] = g_gates[seg0 + m];
        } else {
            stok[tid] = 0;
            sgate[tid] = 0.f;
        }
    }
    __syncthreads();

    int lm = tid >> 1;
    int lk = (tid & 1) * 8;
    int mr = m0 + lm;
    if (mr >= nrows) mr = 0;  // clamp to a written row
    const float* Arow = g_h + (size_t)(seg0 + mr) * HH;
    const float* Brow = W2 + ((size_t)e * DD + (size_t)(n0 + lm)) * HH;

    int tx = tid & 15, ty = tid >> 4;
    float acc[8][8];
#pragma unroll
    for (int i = 0; i < 8; i++)
#pragma unroll
        for (int j = 0; j < 8; j++) acc[i][j] = 0.f;

    for (int k0 = 0; k0 < HH; k0 += BK) {
        float4 a0 = *reinterpret_cast<const float4*>(Arow + k0 + lk);
        float4 a1 = *reinterpret_cast<const float4*>(Arow + k0 + lk + 4);
        float4 c0 = *reinterpret_cast<const float4*>(Brow + k0 + lk);
        float4 c1 = *reinterpret_cast<const float4*>(Brow + k0 + lk + 4);
        __syncthreads();
        As[lk + 0][lm] = a0.x; As[lk + 1][lm] = a0.y; As[lk + 2][lm] = a0.z; As[lk + 3][lm] = a0.w;
        As[lk + 4][lm] = a1.x; As[lk + 5][lm] = a1.y; As[lk + 6][lm] = a1.z; As[lk + 7][lm] = a1.w;
        Bs[lk + 0][lm] = c0.x; Bs[lk + 1][lm] = c0.y; Bs[lk + 2][lm] = c0.z; Bs[lk + 3][lm] = c0.w;
        Bs[lk + 4][lm] = c1.x; Bs[lk + 5][lm] = c1.y; Bs[lk + 6][lm] = c1.z; Bs[lk + 7][lm] = c1.w;
        __syncthreads();
#pragma unroll
        for (int kk = 0; kk < BK; kk++) {
            float4 ra0 = *reinterpret_cast<const float4*>(&As[kk][ty * 8]);
            float4 ra1 = *reinterpret_cast<const float4*>(&As[kk][ty * 8 + 4]);
            float4 rb0 = *reinterpret_cast<const float4*>(&Bs[kk][tx * 8]);
            float4 rb1 = *reinterpret_cast<const float4*>(&Bs[kk][tx * 8 + 4]);
            float ra[8] = {ra0.x, ra0.y, ra0.z, ra0.w, ra1.x, ra1.y, ra1.z, ra1.w};
            float rb[8] = {rb0.x, rb0.y, rb0.z, rb0.w, rb1.x, rb1.y, rb1.z, rb1.w};
#pragma unroll
            for (int i = 0; i < 8; i++)
#pragma unroll
                for (int j = 0; j < 8; j++) acc[i][j] += ra[i] * rb[j];
        }
    }

    const float* b2e = b2 + (size_t)e * DD + n0 + tx * 8;
    float bj[8];
#pragma unroll
    for (int j = 0; j < 8; j++) bj[j] = b2e[j];

#pragma unroll
    for (int i = 0; i < 8; i++) {
        int m = ty * 8 + i;
        if (m0 + m < nrows) {
            int tok = stok[m];
            float gt = sgate[m];
            float* orow = out + (size_t)tok * DD + n0 + tx * 8;
#pragma unroll
            for (int j = 0; j < 8; j++)
                atomicAdd(&orow[j], gt * (acc[i][j] + bj[j]));
        }
    }
}

// ---------------- launch ----------------
extern "C" void kernel_launch(void* const* d_in, const int* in_sizes, int n_in,
                              void* d_out, int out_size) {
    const float* x  = (const float*)d_in[0];
    const float* W1 = (const float*)d_in[1];
    const float* b1 = (const float*)d_in[2];
    const float* W2 = (const float*)d_in[3];
    const float* b2 = (const float*)d_in[4];
    const float* Wc = (const float*)d_in[5];
    const float* bc = (const float*)d_in[6];
    float* out = (float*)d_out;

    cudaMemsetAsync(d_out, 0, (size_t)out_size * sizeof(float), 0);
    init_k<<<1, 32>>>();
    router_k<<<TT / 8, 256>>>(x, Wc, bc);
    scan_k<<<1, 32>>>();
    scatter_k<<<TT / 256, 256>>>();
    gemm1_k<<<dim3(HH / BN, TT / BM, NE), 256>>>(x, W1, b1);
    gemm2_k<<<dim3(DD / BN, TT / BM, NE), 256>>>(W2, b2, out);
}

// round 3
// speedup vs baseline: 4.9244x; 4.9244x over previous
#include <cuda_runtime.h>
#include <cuda_fp16.h>
#include <math.h>
#include <stdint.h>

// Problem constants
#define TT 4096   // tokens
#define DD 1024   // input dim
#define HH 4096   // hidden dim
#define NE 8      // experts
#define NR (TT*2) // total routed rows (top-2)

// ---------------- device scratch ----------------
static __device__ __half g_w1h[(size_t)NE * HH * DD];  // 64 MB
static __device__ __half g_w2h[(size_t)NE * DD * HH];  // 64 MB
static __device__ __half g_xh[(size_t)TT * DD];        // 8 MB
static __device__ __half g_h16[(size_t)NR * HH];       // 64 MB
static __device__ int   g_rows[NR];
static __device__ float g_gates[NR];
static __device__ int   g_tope[TT * 2];
static __device__ float g_topp[TT * 2];
static __device__ int   g_counts[NE];
static __device__ int   g_seg[NE + 1];
static __device__ int   g_cursor[NE];

// ---------------- PTX helpers ----------------
__device__ __forceinline__ uint32_t smem_u32(const void* p) {
    uint32_t a;
    asm("{ .reg .u64 t; cvta.to.shared.u64 t, %1; cvt.u32.u64 %0, t; }" : "=r"(a) : "l"(p));
    return a;
}
__device__ __forceinline__ void ldsm_x4(uint32_t& r0, uint32_t& r1, uint32_t& r2, uint32_t& r3, uint32_t a) {
    asm volatile("ldmatrix.sync.aligned.m8n8.x4.shared.b16 {%0,%1,%2,%3}, [%4];"
                 : "=r"(r0), "=r"(r1), "=r"(r2), "=r"(r3) : "r"(a));
}
__device__ __forceinline__ void ldsm_x2(uint32_t& r0, uint32_t& r1, uint32_t a) {
    asm volatile("ldmatrix.sync.aligned.m8n8.x2.shared.b16 {%0,%1}, [%2];"
                 : "=r"(r0), "=r"(r1) : "r"(a));
}
__device__ __forceinline__ void mma16816(float* d, uint32_t a0, uint32_t a1, uint32_t a2, uint32_t a3,
                                         uint32_t b0, uint32_t b1) {
    asm volatile("mma.sync.aligned.m16n8k16.row.col.f32.f16.f16.f32 "
                 "{%0,%1,%2,%3}, {%4,%5,%6,%7}, {%8,%9}, {%0,%1,%2,%3};"
                 : "+f"(d[0]), "+f"(d[1]), "+f"(d[2]), "+f"(d[3])
                 : "r"(a0), "r"(a1), "r"(a2), "r"(a3), "r"(b0), "r"(b1));
}

// ---------------- tiny setup kernels ----------------
__global__ void init_k() { int i = threadIdx.x; if (i < NE) g_counts[i] = 0; }

__global__ void router_k(const float* __restrict__ x, const float* __restrict__ Wc,
                         const float* __restrict__ bc) {
    __shared__ float sWc[NE * DD];
    for (int i = threadIdx.x; i < NE * DD; i += blockDim.x) sWc[i] = Wc[i];
    __syncthreads();
    int warp = threadIdx.x >> 5, lane = threadIdx.x & 31;
    int t = blockIdx.x * 8 + warp;
    if (t >= TT) return;
    float acc[NE];
#pragma unroll
    for (int e = 0; e < NE; e++) acc[e] = 0.f;
    const float* xr = x + (size_t)t * DD;
    for (int d = lane; d < DD; d += 32) {
        float xv = xr[d];
#pragma unroll
        for (int e = 0; e < NE; e++) acc[e] += xv * sWc[e * DD + d];
    }
#pragma unroll
    for (int e = 0; e < NE; e++)
#pragma unroll
        for (int o = 16; o; o >>= 1) acc[e] += __shfl_xor_sync(0xffffffffu, acc[e], o);
    if (lane == 0) {
        float l[NE], p[NE], mx = -1e30f;
#pragma unroll
        for (int e = 0; e < NE; e++) { l[e] = acc[e] + bc[e]; mx = fmaxf(mx, l[e]); }
        float s = 0.f;
#pragma unroll
        for (int e = 0; e < NE; e++) { p[e] = expf(l[e] - mx); s += p[e]; }
        float inv = 1.f / s;
#pragma unroll
        for (int e = 0; e < NE; e++) p[e] *= inv;
        int i0 = 0;
#pragma unroll
        for (int e = 1; e < NE; e++) if (p[e] > p[i0]) i0 = e;
        int i1 = (i0 == 0) ? 1 : 0;
#pragma unroll
        for (int e = 0; e < NE; e++) if (e != i0 && p[e] > p[i1]) i1 = e;
        g_tope[2 * t] = i0; g_topp[2 * t] = p[i0];
        g_tope[2 * t + 1] = i1; g_topp[2 * t + 1] = p[i1];
        atomicAdd(&g_counts[i0], 1);
        atomicAdd(&g_counts[i1], 1);
    }
}

__global__ void scan_k() {
    if (threadIdx.x == 0) {
        int s = 0;
        for (int e = 0; e < NE; e++) { g_seg[e] = s; g_cursor[e] = s; s += g_counts[e]; }
        g_seg[NE] = s;
    }
}

__global__ void scatter_k() {
    int t = blockIdx.x * blockDim.x + threadIdx.x;
    if (t >= TT) return;
#pragma unroll
    for (int k = 0; k < 2; k++) {
        int e = g_tope[2 * t + k];
        int pos = atomicAdd(&g_cursor[e], 1);
        g_rows[pos] = t;
        g_gates[pos] = g_topp[2 * t + k];
    }
}

// fp32 -> fp16: 8 floats per thread
__global__ void cvt_k(const float4* __restrict__ s, uint4* __restrict__ d) {
    int i = blockIdx.x * blockDim.x + threadIdx.x;
    float4 a = s[2 * i], b = s[2 * i + 1];
    union { uint4 u; __half2 h[4]; } o;
    o.h[0] = __floats2half2_rn(a.x, a.y);
    o.h[1] = __floats2half2_rn(a.z, a.w);
    o.h[2] = __floats2half2_rn(b.x, b.y);
    o.h[3] = __floats2half2_rn(b.z, b.w);
    d[i] = o.u;
}

// ---------------- HMMA GEMM tiles ----------------
// Block tile 128x128, K-chunk 64 halves (128B SW128-swizzled smem rows).
// 8 warps as 2(M) x 4(N); warp tile 64x32 = 4 mfrag(16) x 4 nfrag(8).
#define BM 128
#define BN 128
#define BK 64

// GEMM1: h[r,n] = relu(x[tok[r],:] . W1[e,n,:] + b1[e,n])
__global__ __launch_bounds__(256)
void gemm1_mma(const float* __restrict__ b1) {
    int e = blockIdx.z;
    int seg0 = g_seg[e];
    int nrows = g_seg[e + 1] - seg0;
    int m0 = blockIdx.y * BM;
    if (m0 >= nrows) return;
    int n0 = blockIdx.x * BN;

    __shared__ __align__(1024) __half sA[BM * BK];
    __shared__ __align__(1024) __half sB[BN * BK];
    __shared__ int stok[BM];
    __shared__ float sbias[BN];

    int tid = threadIdx.x, wid = tid >> 5, lane = tid & 31;
    if (tid < BM) {
        int m = m0 + tid;
        stok[tid] = (m < nrows) ? g_rows[seg0 + m] : 0;
        sbias[tid] = b1[(size_t)e * HH + n0 + tid];
    }
    __syncthreads();

    int r = tid >> 1, hb = tid & 1;
    const __half* aRow = g_xh + (size_t)stok[r] * DD;
    const __half* bRow = g_w1h + ((size_t)e * HH + (size_t)(n0 + r)) * DD;

    uint32_t uA = smem_u32(sA), uB = smem_u32(sB);
    int warpM = wid & 1, warpN = wid >> 1;

    // per-lane ldmatrix base addresses
    uint32_t aBase[4], aXor[4];
#pragma unroll
    for (int i = 0; i < 4; i++) {
        int row = warpM * 64 + i * 16 + (lane & 15);
        aBase[i] = uA + row * 128;
        aXor[i] = (uint32_t)(row & 7);
    }
    uint32_t bBase[4], bXor[4];
#pragma unroll
    for (int j = 0; j < 4; j++) {
        int row = warpN * 32 + j * 8 + (lane & 7);
        bBase[j] = uB + row * 128;
        bXor[j] = (uint32_t)(row & 7);
    }
    uint32_t aSub = (uint32_t)(lane >> 4);        // k chunk for A ldmatrix
    uint32_t bSub = (uint32_t)((lane >> 3) & 1);  // k chunk for B ldmatrix

    float acc[4][4][4];
#pragma unroll
    for (int i = 0; i < 4; i++)
#pragma unroll
        for (int j = 0; j < 4; j++)
#pragma unroll
            for (int q = 0; q < 4; q++) acc[i][j][q] = 0.f;

    uint32_t stOff[4];
#pragma unroll
    for (int v = 0; v < 4; v++) {
        int chunk = hb * 4 + v;
        stOff[v] = (uint32_t)(r * 128 + ((chunk ^ (r & 7)) << 4));
    }

    const int NK = DD / BK;   // 16
    for (int kt = 0; kt < NK; kt++) {
        uint4 ga[4], gb[4];
        const uint4* gAp = (const uint4*)(aRow + kt * BK + hb * 32);
        const uint4* gBp = (const uint4*)(bRow + kt * BK + hb * 32);
#pragma unroll
        for (int v = 0; v < 4; v++) { ga[v] = gAp[v]; gb[v] = gBp[v]; }
        __syncthreads();
#pragma unroll
        for (int v = 0; v < 4; v++) {
            *(uint4*)((char*)sA + stOff[v]) = ga[v];
            *(uint4*)((char*)sB + stOff[v]) = gb[v];
        }
        __syncthreads();
#pragma unroll
        for (int ks = 0; ks < 4; ks++) {
            uint32_t af[4][4], bf[4][2];
#pragma unroll
            for (int i = 0; i < 4; i++)
                ldsm_x4(af[i][0], af[i][1], af[i][2], af[i][3],
                        aBase[i] + ((((uint32_t)(ks * 2) + aSub) ^ aXor[i]) << 4));
#pragma unroll
            for (int j = 0; j < 4; j++)
                ldsm_x2(bf[j][0], bf[j][1],
                        bBase[j] + ((((uint32_t)(ks * 2) + bSub) ^ bXor[j]) << 4));
#pragma unroll
            for (int i = 0; i < 4; i++)
#pragma unroll
                for (int j = 0; j < 4; j++)
                    mma16816(acc[i][j], af[i][0], af[i][1], af[i][2], af[i][3], bf[j][0], bf[j][1]);
        }
    }

    // epilogue: relu(acc + bias) -> fp16 pairs
#pragma unroll
    for (int i = 0; i < 4; i++) {
        int r0 = warpM * 64 + i * 16 + (lane >> 2);
#pragma unroll
        for (int j = 0; j < 4; j++) {
            int cc = warpN * 32 + j * 8 + (lane & 3) * 2;
            float bl = sbias[cc], bh = sbias[cc + 1];
            if (m0 + r0 < nrows) {
                __half2 h = __floats2half2_rn(fmaxf(acc[i][j][0] + bl, 0.f),
                                              fmaxf(acc[i][j][1] + bh, 0.f));
                *(__half2*)(g_h16 + (size_t)(seg0 + m0 + r0) * HH + n0 + cc) = h;
            }
            if (m0 + r0 + 8 < nrows) {
                __half2 h = __floats2half2_rn(fmaxf(acc[i][j][2] + bl, 0.f),
                                              fmaxf(acc[i][j][3] + bh, 0.f));
                *(__half2*)(g_h16 + (size_t)(seg0 + m0 + r0 + 8) * HH + n0 + cc) = h;
            }
        }
    }
}

// GEMM2: out[tok,n] += gate * (h[r,:] . W2[e,n,:] + b2[e,n])
__global__ __launch_bounds__(256)
void gemm2_mma(const float* __restrict__ b2, float* __restrict__ out) {
    int e = blockIdx.z;
    int seg0 = g_seg[e];
    int nrows = g_seg[e + 1] - seg0;
    int m0 = blockIdx.y * BM;
    if (m0 >= nrows) return;
    int n0 = blockIdx.x * BN;

    __shared__ __align__(1024) __half sA[BM * BK];
    __shared__ __align__(1024) __half sB[BN * BK];
    __shared__ int stok[BM];
    __shared__ float sgate[BM];
    __shared__ float sbias[BN];

    int tid = threadIdx.x, wid = tid >> 5, lane = tid & 31;
    if (tid < BM) {
        int m = m0 + tid;
        if (m < nrows) { stok[tid] = g_rows[seg0 + m]; sgate[tid] = g_gates[seg0 + m]; }
        else           { stok[tid] = 0; sgate[tid] = 0.f; }
        sbias[tid] = b2[(size_t)e * DD + n0 + tid];
    }
    __syncthreads();

    int r = tid >> 1, hb = tid & 1;
    int mr = m0 + r; if (mr >= nrows) mr = nrows - 1;
    const __half* aRow = g_h16 + (size_t)(seg0 + mr) * HH;
    const __half* bRow = g_w2h + ((size_t)e * DD + (size_t)(n0 + r)) * HH;

    uint32_t uA = smem_u32(sA), uB = smem_u32(sB);
    int warpM = wid & 1, warpN = wid >> 1;

    uint32_t aBase[4], aXor[4];
#pragma unroll
    for (int i = 0; i < 4; i++) {
        int row = warpM * 64 + i * 16 + (lane & 15);
        aBase[i] = uA + row * 128;
        aXor[i] = (uint32_t)(row & 7);
    }
    uint32_t bBase[4], bXor[4];
#pragma unroll
    for (int j = 0; j < 4; j++) {
        int row = warpN * 32 + j * 8 + (lane & 7);
        bBase[j] = uB + row * 128;
        bXor[j] = (uint32_t)(row & 7);
    }
    uint32_t aSub = (uint32_t)(lane >> 4);
    uint32_t bSub = (uint32_t)((lane >> 3) & 1);

    float acc[4][4][4];
#pragma unroll
    for (int i = 0; i < 4; i++)
#pragma unroll
        for (int j = 0; j < 4; j++)
#pragma unroll
            for (int q = 0; q < 4; q++) acc[i][j][q] = 0.f;

    uint32_t stOff[4];
#pragma unroll
    for (int v = 0; v < 4; v++) {
        int chunk = hb * 4 + v;
        stOff[v] = (uint32_t)(r * 128 + ((chunk ^ (r & 7)) << 4));
    }

    const int NK = HH / BK;   // 64
    for (int kt = 0; kt < NK; kt++) {
        uint4 ga[4], gb[4];
        const uint4* gAp = (const uint4*)(aRow + kt * BK + hb * 32);
        const uint4* gBp = (const uint4*)(bRow + kt * BK + hb * 32);
#pragma unroll
        for (int v = 0; v < 4; v++) { ga[v] = gAp[v]; gb[v] = gBp[v]; }
        __syncthreads();
#pragma unroll
        for (int v = 0; v < 4; v++) {
            *(uint4*)((char*)sA + stOff[v]) = ga[v];
            *(uint4*)((char*)sB + stOff[v]) = gb[v];
        }
        __syncthreads();
#pragma unroll
        for (int ks = 0; ks < 4; ks++) {
            uint32_t af[4][4], bf[4][2];
#pragma unroll
            for (int i = 0; i < 4; i++)
                ldsm_x4(af[i][0], af[i][1], af[i][2], af[i][3],
                        aBase[i] + ((((uint32_t)(ks * 2) + aSub) ^ aXor[i]) << 4));
#pragma unroll
            for (int j = 0; j < 4; j++)
                ldsm_x2(bf[j][0], bf[j][1],
                        bBase[j] + ((((uint32_t)(ks * 2) + bSub) ^ bXor[j]) << 4));
#pragma unroll
            for (int i = 0; i < 4; i++)
#pragma unroll
                for (int j = 0; j < 4; j++)
                    mma16816(acc[i][j], af[i][0], af[i][1], af[i][2], af[i][3], bf[j][0], bf[j][1]);
        }
    }

    // epilogue: atomicAdd gate*(acc+bias)
#pragma unroll
    for (int i = 0; i < 4; i++) {
        int r0 = warpM * 64 + i * 16 + (lane >> 2);
#pragma unroll
        for (int j = 0; j < 4; j++) {
            int cc = warpN * 32 + j * 8 + (lane & 3) * 2;
            float bl = sbias[cc], bh = sbias[cc + 1];
            if (m0 + r0 < nrows) {
                float gt = sgate[r0];
                float* orow = out + (size_t)stok[r0] * DD + n0 + cc;
                atomicAdd(orow,     gt * (acc[i][j][0] + bl));
                atomicAdd(orow + 1, gt * (acc[i][j][1] + bh));
            }
            if (m0 + r0 + 8 < nrows) {
                float gt = sgate[r0 + 8];
                float* orow = out + (size_t)stok[r0 + 8] * DD + n0 + cc;
                atomicAdd(orow,     gt * (acc[i][j][2] + bl));
                atomicAdd(orow + 1, gt * (acc[i][j][3] + bh));
            }
        }
    }
}

// ---------------- launch ----------------
extern "C" void kernel_launch(void* const* d_in, const int* in_sizes, int n_in,
                              void* d_out, int out_size) {
    const float* x  = (const float*)d_in[0];
    const float* W1 = (const float*)d_in[1];
    const float* b1 = (const float*)d_in[2];
    const float* W2 = (const float*)d_in[3];
    const float* b2 = (const float*)d_in[4];
    const float* Wc = (const float*)d_in[5];
    const float* bc = (const float*)d_in[6];
    float* out = (float*)d_out;

    __half *w1h, *w2h, *xh;
    cudaGetSymbolAddress((void**)&w1h, g_w1h);
    cudaGetSymbolAddress((void**)&w2h, g_w2h);
    cudaGetSymbolAddress((void**)&xh, g_xh);

    cudaMemsetAsync(d_out, 0, (size_t)out_size * sizeof(float), 0);
    init_k<<<1, 32>>>();
    router_k<<<TT / 8, 256>>>(x, Wc, bc);
    scan_k<<<1, 32>>>();
    scatter_k<<<TT / 256, 256>>>();
    cvt_k<<<(TT * DD) / 8 / 256, 256>>>((const float4*)x, (uint4*)xh);
    cvt_k<<<((size_t)NE * HH * DD) / 8 / 256, 256>>>((const float4*)W1, (uint4*)w1h);
    cvt_k<<<((size_t)NE * DD * HH) / 8 / 256, 256>>>((const float4*)W2, (uint4*)w2h);
    gemm1_mma<<<dim3(HH / BN, TT / BM, NE), 256>>>(b1);
    gemm2_mma<<<dim3(DD / BN, TT / BM, NE), 256>>>(b2, out);
}